// round 1
// baseline (speedup 1.0000x reference)
#include <cuda_runtime.h>
#include <math.h>

#define NN 20000
#define EE 320000
#define FI 128
#define HDIM 32
#define KORD 32
#define HD2 64   // z||h concatenated outputs

// ---------------- static device scratch (no runtime allocation) ----------------
__device__ int   g_deg[NN];
__device__ float g_dis[NN];
__device__ int   g_rowcnt[NN];
__device__ int   g_rowptr[NN + 1];
__device__ int   g_rowfill[NN];
__device__ int   g_csr_src[EE];
__device__ float g_csr_w[EE];
__device__ float g_Wall[FI * KORD * HD2];           // [128][2048] repacked weights
__device__ float g_Y[(size_t)KORD * NN * HD2];      // y_k = x @ W_k, 163.84 MB
__device__ float g_B[3][NN * HD2];                  // Clenshaw ring buffers
__device__ float g_h[NN * HDIM];
__device__ float g_xp[NN * HDIM];
__device__ float g_asv[NN];
__device__ float g_adv[NN];
__device__ float g_u[NN];
__device__ float g_v[NN];
__device__ float g_p[HDIM];
__device__ float g_q[HDIM];
__device__ float g_cuv[2];

// ---------------- setup kernels ----------------
__global__ void k_zero() {
    int i = blockIdx.x * blockDim.x + threadIdx.x;
    int stride = gridDim.x * blockDim.x;
    for (int t = i; t < NN; t += stride) { g_deg[t] = 0; g_rowcnt[t] = 0; g_rowfill[t] = 0; }
    for (int t = i; t < NN * HD2; t += stride) { g_B[1][t] = 0.f; g_B[2][t] = 0.f; }
}

__global__ void k_hist(const int* __restrict__ ei) {
    int e = blockIdx.x * blockDim.x + threadIdx.x;
    if (e >= EE) return;
    atomicAdd(&g_deg[ei[e]], 1);        // out-degree over src
    atomicAdd(&g_rowcnt[ei[EE + e]], 1); // in-count over dst (CSR rows)
}

// single block: dis + exclusive scan of rowcnt -> rowptr
__global__ void k_scan() {
    __shared__ int ssum[1024];
    int t = threadIdx.x;
    const int CH = 20; // 1024*20 >= 20000
    int base = t * CH;
    int s = 0;
    for (int i = 0; i < CH; i++) { int idx = base + i; if (idx < NN) s += g_rowcnt[idx]; }
    ssum[t] = s; __syncthreads();
    for (int off = 1; off < 1024; off <<= 1) {
        int v = (t >= off) ? ssum[t - off] : 0;
        __syncthreads();
        ssum[t] += v;
        __syncthreads();
    }
    int run = (t > 0) ? ssum[t - 1] : 0;
    for (int i = 0; i < CH; i++) {
        int idx = base + i;
        if (idx < NN) { g_rowptr[idx] = run; run += g_rowcnt[idx]; }
    }
    if (t == 1023) g_rowptr[NN] = EE;
    for (int i = 0; i < CH; i++) {
        int idx = base + i;
        if (idx < NN) {
            int d = g_deg[idx];
            g_dis[idx] = (d > 0) ? rsqrtf((float)d) : 0.f;
        }
    }
}

__global__ void k_scatter(const int* __restrict__ ei) {
    int e = blockIdx.x * blockDim.x + threadIdx.x;
    if (e >= EE) return;
    int s = ei[e], d = ei[EE + e];
    int pos = g_rowptr[d] + atomicAdd(&g_rowfill[d], 1);
    g_csr_src[pos] = s;
    g_csr_w[pos] = -g_dis[s] * g_dis[d];
}

// repack [K,F,32]+[K,F,32] -> Wall[f][k*64+j]
__global__ void k_prep_wall(const float* __restrict__ Wxz, const float* __restrict__ Wxh) {
    int idx = blockIdx.x * blockDim.x + threadIdx.x;
    if (idx >= FI * KORD * HD2) return;
    int f = idx / (KORD * HD2);
    int c = idx % (KORD * HD2);
    int k = c >> 6;
    int j = c & 63;
    g_Wall[idx] = (j < HDIM) ? Wxz[(k * FI + f) * HDIM + j]
                             : Wxh[(k * FI + f) * HDIM + (j - HDIM)];
}

// p = W_emb @ W_cls[:128], q = W_emb @ W_cls[128:], cuv = b_emb . W_cls halves
__global__ void k_prep_pq(const float* __restrict__ Wemb, const float* __restrict__ bemb,
                          const float* __restrict__ Wcls) {
    int t = threadIdx.x; // 64
    int i = t & 31;
    const float* wc = Wcls + ((t < 32) ? 0 : 128);
    float s = 0.f;
    for (int d = 0; d < 128; d++) s += Wemb[i * 128 + d] * wc[d];
    if (t < 32) g_p[i] = s; else g_q[i] = s;
    if (t < 2) {
        const float* w2 = Wcls + t * 128;
        float c = 0.f;
        for (int d = 0; d < 128; d++) c += bemb[d] * w2[d];
        g_cuv[t] = c;
    }
}

// ---------------- Y = x @ Wall : [20000,128] @ [128,2048], tile 64x64, k-chunks of 64
__global__ void __launch_bounds__(256) k_gemm(const float* __restrict__ x) {
    __shared__ float xs[64][68]; // [f][node] transposed, padded for fp4 alignment
    __shared__ float ws[64][64]; // [f][j]
    int n0 = blockIdx.x * 64;
    int cb = blockIdx.y;      // k index (col tile = k*64..k*64+63)
    int c0 = cb * 64;
    int tid = threadIdx.x;
    int tx = tid & 15, ty = tid >> 4;
    float acc[4][4] = {};
    for (int kc = 0; kc < 2; kc++) {
#pragma unroll
        for (int it = 0; it < 4; it++) {
            int li = tid + it * 256;   // 0..1023
            int r  = li >> 4;          // 0..63
            int q4 = li & 15;          // float4 within row
            int gn = n0 + r;
            float4 v = make_float4(0.f, 0.f, 0.f, 0.f);
            if (gn < NN) v = *(const float4*)(x + (size_t)gn * FI + kc * 64 + q4 * 4);
            xs[q4 * 4 + 0][r] = v.x; xs[q4 * 4 + 1][r] = v.y;
            xs[q4 * 4 + 2][r] = v.z; xs[q4 * 4 + 3][r] = v.w;
            float4 w = *(const float4*)(g_Wall + (size_t)(kc * 64 + r) * (KORD * HD2) + c0 + q4 * 4);
            *(float4*)&ws[r][q4 * 4] = w;
        }
        __syncthreads();
#pragma unroll
        for (int f = 0; f < 64; f++) {
            float4 a = *(const float4*)&xs[f][ty * 4];
            float4 b = *(const float4*)&ws[f][tx * 4];
            acc[0][0] += a.x * b.x; acc[0][1] += a.x * b.y; acc[0][2] += a.x * b.z; acc[0][3] += a.x * b.w;
            acc[1][0] += a.y * b.x; acc[1][1] += a.y * b.y; acc[1][2] += a.y * b.z; acc[1][3] += a.y * b.w;
            acc[2][0] += a.z * b.x; acc[2][1] += a.z * b.y; acc[2][2] += a.z * b.z; acc[2][3] += a.z * b.w;
            acc[3][0] += a.w * b.x; acc[3][1] += a.w * b.y; acc[3][2] += a.w * b.z; acc[3][3] += a.w * b.w;
        }
        __syncthreads();
    }
#pragma unroll
    for (int r = 0; r < 4; r++) {
        int gn = n0 + ty * 4 + r;
        if (gn < NN) {
            float4 o = make_float4(acc[r][0], acc[r][1], acc[r][2], acc[r][3]);
            *(float4*)(g_Y + ((size_t)cb * NN + gn) * HD2 + tx * 4) = o;
        }
    }
}

// ---------------- Clenshaw step: b_new = Y[k] + 2*L*b1 - b2 (warp per node, float2/lane)
__global__ void k_cheb_step(int k, int ibn, int ib1, int ib2) {
    int gw = (blockIdx.x * blockDim.x + threadIdx.x) >> 5;
    int lane = threadIdx.x & 31;
    if (gw >= NN) return;
    const float* yk = g_Y + (size_t)k * NN * HD2;
    const float* b1 = g_B[ib1];
    const float* b2 = g_B[ib2];
    float* bn = g_B[ibn];
    int rs = g_rowptr[gw], re = g_rowptr[gw + 1];
    int j = lane * 2;
    float ax = 0.f, ay = 0.f;
    for (int e = rs; e < re; e++) {
        int s = g_csr_src[e];
        float w = g_csr_w[e];
        float2 v = *(const float2*)(b1 + (size_t)s * HD2 + j);
        ax += w * v.x; ay += w * v.y;
    }
    float2 y = *(const float2*)(yk + (size_t)gw * HD2 + j);
    float2 p = *(const float2*)(b2 + (size_t)gw * HD2 + j);
    float2 o;
    o.x = y.x + 2.f * ax - p.x;
    o.y = y.y + 2.f * ay - p.y;
    *(float2*)(bn + (size_t)gw * HD2 + j) = o;
}

// final: out64 = Y[0] + L*b1 - b2 ; then h = (1-sigmoid(z_pre))*tanh(h_pre)
__global__ void k_cheb_final(int ib1, int ib2,
                             const float* __restrict__ bxz, const float* __restrict__ bhz,
                             const float* __restrict__ bxh, const float* __restrict__ bhh) {
    int gw = (blockIdx.x * blockDim.x + threadIdx.x) >> 5;
    int lane = threadIdx.x & 31;
    if (gw >= NN) return;
    const float* y0 = g_Y;
    const float* b1 = g_B[ib1];
    const float* b2 = g_B[ib2];
    int rs = g_rowptr[gw], re = g_rowptr[gw + 1];
    int j = lane * 2;
    float ax = 0.f, ay = 0.f;
    for (int e = rs; e < re; e++) {
        int s = g_csr_src[e];
        float w = g_csr_w[e];
        float2 v = *(const float2*)(b1 + (size_t)s * HD2 + j);
        ax += w * v.x; ay += w * v.y;
    }
    float2 y = *(const float2*)(y0 + (size_t)gw * HD2 + j);
    float2 p = *(const float2*)(b2 + (size_t)gw * HD2 + j);
    float ox = y.x + ax - p.x;
    float oy = y.y + ay - p.y;
    // lanes 0..15 hold z columns (0..31), 16..31 hold h columns (32..63)
    float px = __shfl_xor_sync(0xffffffffu, ox, 16);
    float py = __shfl_xor_sync(0xffffffffu, oy, 16);
    if (lane < 16) {
        int j0 = lane * 2;
        float z0 = 1.f / (1.f + __expf(-(ox + bxz[j0] + bhz[j0])));
        float z1 = 1.f / (1.f + __expf(-(oy + bxz[j0 + 1] + bhz[j0 + 1])));
        float t0 = tanhf(px + bxh[j0] + bhh[j0]);
        float t1 = tanhf(py + bxh[j0 + 1] + bhh[j0 + 1]);
        float2 hh;
        hh.x = (1.f - z0) * t0;
        hh.y = (1.f - z1) * t1;
        *(float2*)(g_h + (size_t)gw * HDIM + j0) = hh;
    }
}

// ---------------- GAT ----------------
__global__ void k_xp(const float* __restrict__ Wg, const float* __restrict__ asrc,
                     const float* __restrict__ adst) {
    int gw = (blockIdx.x * blockDim.x + threadIdx.x) >> 5;
    int lane = threadIdx.x & 31;
    if (gw >= NN) return;
    float hv = g_h[(size_t)gw * HDIM + lane];
    float xpv = 0.f;
#pragma unroll
    for (int i = 0; i < 32; i++)
        xpv += __shfl_sync(0xffffffffu, hv, i) * Wg[i * HDIM + lane];
    g_xp[(size_t)gw * HDIM + lane] = xpv;
    float a = xpv * asrc[lane];
    float b = xpv * adst[lane];
#pragma unroll
    for (int off = 16; off; off >>= 1) {
        a += __shfl_xor_sync(0xffffffffu, a, off);
        b += __shfl_xor_sync(0xffffffffu, b, off);
    }
    if (lane == 0) { g_asv[gw] = a; g_adv[gw] = b; }
}

// online-softmax GAT aggregation per dst node, then fold emb+classifier into u,v
__global__ void k_gat(const float* __restrict__ bgat) {
    int gw = (blockIdx.x * blockDim.x + threadIdx.x) >> 5;
    int lane = threadIdx.x & 31;
    if (gw >= NN) return;
    float advd = g_adv[gw];
    float xpd = g_xp[(size_t)gw * HDIM + lane];
    float es = g_asv[gw] + advd;               // self loop score
    es = es > 0.f ? es : 0.2f * es;
    float m = es, ssum = 1.f, acc = xpd;
    int rs = g_rowptr[gw], re = g_rowptr[gw + 1];
    for (int e = rs; e < re; e++) {
        int s = g_csr_src[e];
        float sc = g_asv[s] + advd;
        sc = sc > 0.f ? sc : 0.2f * sc;
        float xv = g_xp[(size_t)s * HDIM + lane];
        float nm = fmaxf(m, sc);
        float r = __expf(m - nm);
        float w = __expf(sc - nm);
        ssum = ssum * r + w;
        acc = acc * r + w * xv;
        m = nm;
    }
    float h2 = acc / ssum + bgat[lane];
    h2 = fmaxf(h2, 0.f);
    float a = h2 * g_p[lane];
    float b = h2 * g_q[lane];
#pragma unroll
    for (int off = 16; off; off >>= 1) {
        a += __shfl_xor_sync(0xffffffffu, a, off);
        b += __shfl_xor_sync(0xffffffffu, b, off);
    }
    if (lane == 0) { g_u[gw] = a + g_cuv[0]; g_v[gw] = b + g_cuv[1]; }
}

__global__ void k_out(const int* __restrict__ ei, const float* __restrict__ bcls,
                      float* __restrict__ out) {
    int e = blockIdx.x * blockDim.x + threadIdx.x;
    if (e >= EE) return;
    out[e] = g_u[ei[e]] + g_v[ei[EE + e]] + bcls[0];
}

// ---------------- launch ----------------
extern "C" void kernel_launch(void* const* d_in, const int* in_sizes, int n_in,
                              void* d_out, int out_size) {
    const float* x    = (const float*)d_in[0];
    const int*   ei   = (const int*)d_in[1];
    const float* Wxz  = (const float*)d_in[2];
    const float* Wxh  = (const float*)d_in[6];
    const float* bxz  = (const float*)d_in[8];
    const float* bhz  = (const float*)d_in[9];
    const float* bxh  = (const float*)d_in[12];
    const float* bhh  = (const float*)d_in[13];
    const float* Wgat = (const float*)d_in[14];
    const float* asrc = (const float*)d_in[15];
    const float* adst = (const float*)d_in[16];
    const float* bgat = (const float*)d_in[17];
    const float* Wemb = (const float*)d_in[18];
    const float* bemb = (const float*)d_in[19];
    const float* Wcls = (const float*)d_in[20];
    const float* bcls = (const float*)d_in[21];
    float* out = (float*)d_out;

    const int EB = (EE + 255) / 256;     // 1250
    const int NB = (NN * 32 + 255) / 256; // 2500 blocks (warp per node)

    k_zero<<<256, 256>>>();
    k_hist<<<EB, 256>>>(ei);
    k_scan<<<1, 1024>>>();
    k_scatter<<<EB, 256>>>(ei);
    k_prep_wall<<<(FI * KORD * HD2) / 256, 256>>>(Wxz, Wxh);
    k_prep_pq<<<1, 64>>>(Wemb, bemb, Wcls);
    k_gemm<<<dim3((NN + 63) / 64, KORD), 256>>>(x);

    int bn = 0, b1 = 1, b2 = 2;
    for (int k = KORD - 1; k >= 1; k--) {
        k_cheb_step<<<NB, 256>>>(k, bn, b1, b2);
        int t = b2; b2 = b1; b1 = bn; bn = t;
    }
    k_cheb_final<<<NB, 256>>>(b1, b2, bxz, bhz, bxh, bhh);
    k_xp<<<NB, 256>>>(Wgat, asrc, adst);
    k_gat<<<NB, 256>>>(bgat);
    k_out<<<EB, 256>>>(ei, bcls, out);
}